// round 12
// baseline (speedup 1.0000x reference)
#include <cuda_runtime.h>
#include <cuda_fp16.h>
#include <cuda_bf16.h>
#include <mma.h>
#include <math.h>

using namespace nvcuda;

// GATNET: N=20000, E=640000, IN=256, H=4, OUT=64
#define NN   20000
#define EE   640000
#define ET   (EE + NN)
#define KIN  256
#define HC   256
#define H1   4
#define C1   64
#define C2   64
#define PAD  64          // row padding so full WMMA tiles can store unguarded

__device__ float  g_h1[(NN + PAD) * HC];
__device__ __half g_h1h[NN * HC];
__device__ float  g_x1[NN * HC];
__device__ float  g_h2[(NN + PAD) * C2];
__device__ __half g_h2h[NN * C2];
__device__ float  g_as1[NN * H1];
__device__ float  g_ad1[NN * H1];
__device__ float  g_as2[NN];
__device__ float  g_ad2[NN];
__device__ int    g_cnt[NN];
__device__ int    g_ptr[NN + 1];
__device__ int    g_cur[NN];
__device__ int    g_csr_src[ET];
__device__ float  g_w1c[ET * H1];
__device__ float  g_w2c[ET];
__device__ int    g_is64;

// ---------------- dtype probe + zero counts (fused) ----------------
__global__ void detect_zero_k(const long long* __restrict__ ei64) {
    int t = blockIdx.x * blockDim.x + threadIdx.x;
    if (t < NN) g_cnt[t] = 0;
    if (blockIdx.x == 0) {
        __shared__ int bad;
        if (threadIdx.x == 0) bad = 0;
        __syncthreads();
        for (int i = threadIdx.x; i < 2048; i += blockDim.x) {
            long long v = ei64[i];
            if (v < 0 || v >= NN) bad = 1;
        }
        __syncthreads();
        if (threadIdx.x == 0) g_is64 = bad ? 0 : 1;
    }
}

__device__ __forceinline__ void load_edge(const void* __restrict__ ei, int e, int& s, int& d) {
    if (e >= EE) { s = d = e - EE; return; }
    if (g_is64) {
        const long long* p = (const long long*)ei;
        s = (int)p[e]; d = (int)p[EE + e];
    } else {
        const int* p = (const int*)ei;
        s = p[e]; d = p[EE + e];
    }
}

__global__ void count_k(const void* __restrict__ ei) {
    int e = blockIdx.x * blockDim.x + threadIdx.x;
    if (e >= ET) return;
    int s, d; load_edge(ei, e, s, d);
    if ((unsigned)d < NN) atomicAdd(&g_cnt[d], 1);
}

// ---------------- fast single-block scan ----------------
__global__ __launch_bounds__(1024) void scan_fast_k() {
    const int T = 20;
    int tid = threadIdx.x;
    int base = tid * T;
    int pre[T];
    int s = 0;
#pragma unroll
    for (int i = 0; i < T; i++) {
        int idx = base + i;
        int v = (idx < NN) ? g_cnt[idx] : 0;
        pre[i] = s; s += v;
    }
    int lane = tid & 31, wid = tid >> 5;
    int incl = s;
#pragma unroll
    for (int o = 1; o < 32; o <<= 1) {
        int n = __shfl_up_sync(0xffffffffu, incl, o);
        if (lane >= o) incl += n;
    }
    __shared__ int wsum[32];
    if (lane == 31) wsum[wid] = incl;
    __syncthreads();
    if (wid == 0) {
        int v = wsum[lane];
        int wi = v;
#pragma unroll
        for (int o = 1; o < 32; o <<= 1) {
            int n = __shfl_up_sync(0xffffffffu, wi, o);
            if (lane >= o) wi += n;
        }
        wsum[lane] = wi - v;
    }
    __syncthreads();
    int off = wsum[wid] + incl - s;
#pragma unroll
    for (int i = 0; i < T; i++) {
        int idx = base + i;
        if (idx < NN) { int p = off + pre[i]; g_ptr[idx] = p; g_cur[idx] = p; }
    }
    if (tid == 1023) g_ptr[NN] = off + s;
}

__global__ void scatter_k(const void* __restrict__ ei) {
    int e = blockIdx.x * blockDim.x + threadIdx.x;
    if (e >= ET) return;
    int s, d; load_edge(ei, e, s, d);
    if ((unsigned)d < NN && (unsigned)s < NN) {
        int pos = atomicAdd(&g_cur[d], 1);
        g_csr_src[pos] = s;
    }
}

// ---------------- split-bf16 WMMA GEMM: C = A@B (fp32 in/out, ~fp32 accuracy) ----------------
// C = Ahi@Bhi + Ahi@Blo + Alo@Bhi  (lo*lo dropped: ~1.5e-5 rel)
// Block: 64x64 tile, 8 warps, each warp two 16x16 output tiles.
#define BM 64
#define BN 64
#define BK 16
__global__ __launch_bounds__(256) void wgemm_k(const float* __restrict__ A,
                                               const float* __restrict__ B,
                                               float* __restrict__ C,
                                               int M, int N, int K) {
    __shared__ __nv_bfloat16 Ah[BM][BK + 8], Al[BM][BK + 8];
    __shared__ __nv_bfloat16 Bh[BK][BN + 8], Bl[BK][BN + 8];
    const int bm = blockIdx.y * BM;
    const int bn = blockIdx.x * BN;
    const int tid = threadIdx.x;
    const int w = tid >> 5;
    const int wm = (w >> 1) * 16;      // warp row tile: 0,16,32,48
    const int wn = (w & 1) * 32;       // warp col base: 0 or 32 (two tiles: wn, wn+16)

    wmma::fragment<wmma::accumulator, 16, 16, 16, float> c0, c1;
    wmma::fill_fragment(c0, 0.f);
    wmma::fill_fragment(c1, 0.f);

    for (int k0 = 0; k0 < K; k0 += BK) {
        for (int i = tid; i < BM * BK; i += 256) {
            int r = i >> 4, c = i & 15;
            int gm = bm + r;
            float v = (gm < M) ? A[(size_t)gm * K + k0 + c] : 0.f;
            __nv_bfloat16 hi = __float2bfloat16(v);
            Ah[r][c] = hi;
            Al[r][c] = __float2bfloat16(v - __bfloat162float(hi));
        }
        for (int i = tid; i < BK * BN; i += 256) {
            int r = i >> 6, c = i & 63;
            float v = B[(size_t)(k0 + r) * N + bn + c];
            __nv_bfloat16 hi = __float2bfloat16(v);
            Bh[r][c] = hi;
            Bl[r][c] = __float2bfloat16(v - __bfloat162float(hi));
        }
        __syncthreads();

        wmma::fragment<wmma::matrix_a, 16, 16, 16, __nv_bfloat16, wmma::row_major> ah, al;
        wmma::fragment<wmma::matrix_b, 16, 16, 16, __nv_bfloat16, wmma::row_major> bh0, bh1, bl0, bl1;
        wmma::load_matrix_sync(ah, &Ah[wm][0], BK + 8);
        wmma::load_matrix_sync(al, &Al[wm][0], BK + 8);
        wmma::load_matrix_sync(bh0, &Bh[0][wn], BN + 8);
        wmma::load_matrix_sync(bh1, &Bh[0][wn + 16], BN + 8);
        wmma::load_matrix_sync(bl0, &Bl[0][wn], BN + 8);
        wmma::load_matrix_sync(bl1, &Bl[0][wn + 16], BN + 8);
        wmma::mma_sync(c0, ah, bh0, c0);
        wmma::mma_sync(c0, ah, bl0, c0);
        wmma::mma_sync(c0, al, bh0, c0);
        wmma::mma_sync(c1, ah, bh1, c1);
        wmma::mma_sync(c1, ah, bl1, c1);
        wmma::mma_sync(c1, al, bh1, c1);
        __syncthreads();
    }

    // C buffers are row-padded by PAD, so full-tile stores are safe at the M edge.
    wmma::store_matrix_sync(&C[(size_t)(bm + wm) * N + bn + wn],      c0, N, wmma::mem_row_major);
    wmma::store_matrix_sync(&C[(size_t)(bm + wm) * N + bn + wn + 16], c1, N, wmma::mem_row_major);
}

// ---------------- attention logits + fp16 copy (fused) ----------------
__global__ void att1_k(const float* __restrict__ att_src, const float* __restrict__ att_dst) {
    int t = blockIdx.x * blockDim.x + threadIdx.x;
    if (t >= NN * H1) return;
    int n = t / H1, h = t % H1;
    const float* row = g_h1 + (size_t)n * HC + h * C1;
    __half2* hh = (__half2*)(g_h1h + (size_t)n * HC + h * C1);
    const float* asv = att_src + h * C1;
    const float* adv = att_dst + h * C1;
    float s = 0.f, d = 0.f;
#pragma unroll 8
    for (int c = 0; c < C1; c += 2) {
        float v0 = row[c], v1 = row[c + 1];
        s += v0 * asv[c] + v1 * asv[c + 1];
        d += v0 * adv[c] + v1 * adv[c + 1];
        hh[c >> 1] = __floats2half2_rn(v0, v1);
    }
    g_as1[t] = s; g_ad1[t] = d;
}

__global__ void att2_k(const float* __restrict__ att_src, const float* __restrict__ att_dst) {
    int n = blockIdx.x * blockDim.x + threadIdx.x;
    if (n >= NN) return;
    const float* row = g_h2 + (size_t)n * C2;
    __half2* hh = (__half2*)(g_h2h + (size_t)n * C2);
    float s = 0.f, d = 0.f;
#pragma unroll 8
    for (int c = 0; c < C2; c += 2) {
        float v0 = row[c], v1 = row[c + 1];
        s += v0 * att_src[c] + v1 * att_src[c + 1];
        d += v0 * att_dst[c] + v1 * att_dst[c + 1];
        hh[c >> 1] = __floats2half2_rn(v0, v1);
    }
    g_as2[n] = s; g_ad2[n] = d;
}

// ---------------- fused edge-softmax + fp16 gather, layer 1 ----------------
__global__ __launch_bounds__(256) void gat1_k(const float* __restrict__ bias1) {
    const int d = blockIdx.x;
    const int tid = threadIdx.x;
    const int p0 = g_ptr[d], p1 = g_ptr[d + 1];
    const int cnt = p1 - p0;

    float loc[H1] = {0.f, 0.f, 0.f, 0.f};
    const int items = cnt * H1;
    for (int i = tid; i < items; i += 256) {
        int j = p0 + (i >> 2);
        int h = i & 3;
        int s = g_csr_src[j];
        float x = g_as1[s * H1 + h] + g_ad1[d * H1 + h];
        x = (x > 0.f) ? x : 0.2f * x;
        x = fmaxf(x, -60.f);
        float w = expf(x);
        g_w1c[j * H1 + h] = w;
        loc[h] += w;
    }
#pragma unroll
    for (int h = 0; h < H1; h++)
#pragma unroll
        for (int o = 16; o; o >>= 1) loc[h] += __shfl_down_sync(0xffffffffu, loc[h], o);
    __shared__ float sw[8][H1];
    if ((tid & 31) == 0)
#pragma unroll
        for (int h = 0; h < H1; h++) sw[tid >> 5][h] = loc[h];
    __syncthreads();
    __shared__ float sinv[H1];
    if (tid < H1) {
        float s = 0.f;
#pragma unroll
        for (int w = 0; w < 8; w++) s += sw[w][tid];
        sinv[tid] = 1.0f / (s + 1e-16f);
    }
    __syncthreads();

    const int eo = tid >> 7;
    const int fi = tid & 127;
    const int f  = fi * 2;
    const int h  = f >> 6;
    const float inv = sinv[h];
    float2 acc = make_float2(0.f, 0.f);
    const __half2* h1h = (const __half2*)g_h1h;
    for (int j = p0 + eo; j < p1; j += 2) {
        int s = g_csr_src[j];
        float w = g_w1c[j * H1 + h];
        float2 v = __half22float2(h1h[(size_t)s * (HC / 2) + fi]);
        acc.x += w * v.x;
        acc.y += w * v.y;
    }
    __shared__ float2 part[128];
    if (eo == 1) part[fi] = acc;
    __syncthreads();
    if (eo == 0) {
        acc.x += part[fi].x;
        acc.y += part[fi].y;
        float v0 = acc.x * inv + bias1[f];
        float v1 = acc.y * inv + bias1[f + 1];
        v0 = (v0 > 0.f) ? v0 : expm1f(v0);
        v1 = (v1 > 0.f) ? v1 : expm1f(v1);
        g_x1[(size_t)d * HC + f]     = v0;
        g_x1[(size_t)d * HC + f + 1] = v1;
    }
}

// ---------------- fused edge-softmax + fp16 gather, layer 2 ----------------
__global__ __launch_bounds__(64) void gat2_k(const float* __restrict__ bias2,
                                             float* __restrict__ out) {
    const int d = blockIdx.x;
    const int tid = threadIdx.x;
    const int p0 = g_ptr[d], p1 = g_ptr[d + 1];
    const int cnt = p1 - p0;

    float loc = 0.f;
    const float ad = g_ad2[d];
    for (int i = tid; i < cnt; i += 64) {
        int j = p0 + i;
        int s = g_csr_src[j];
        float x = g_as2[s] + ad;
        x = (x > 0.f) ? x : 0.2f * x;
        x = fmaxf(x, -60.f);
        float w = expf(x);
        g_w2c[j] = w;
        loc += w;
    }
#pragma unroll
    for (int o = 16; o; o >>= 1) loc += __shfl_down_sync(0xffffffffu, loc, o);
    __shared__ float sw2[2];
    if ((tid & 31) == 0) sw2[tid >> 5] = loc;
    __syncthreads();
    __shared__ float sinv2;
    if (tid == 0) sinv2 = 1.0f / (sw2[0] + sw2[1] + 1e-16f);
    __syncthreads();

    const int eo = tid >> 5;
    const int fi = tid & 31;
    const int f  = fi * 2;
    const float inv = sinv2;
    float2 acc = make_float2(0.f, 0.f);
    const __half2* h2h = (const __half2*)g_h2h;
    for (int j = p0 + eo; j < p1; j += 2) {
        int s = g_csr_src[j];
        float w = g_w2c[j];
        float2 v = __half22float2(h2h[(size_t)s * (C2 / 2) + fi]);
        acc.x += w * v.x;
        acc.y += w * v.y;
    }
    __shared__ float2 part2[32];
    if (eo == 1) part2[fi] = acc;
    __syncthreads();
    if (eo == 0) {
        acc.x += part2[fi].x;
        acc.y += part2[fi].y;
        out[(size_t)d * C2 + f]     = acc.x * inv + bias2[f];
        out[(size_t)d * C2 + f + 1] = acc.y * inv + bias2[f + 1];
    }
}

// ---------------- launch ----------------
extern "C" void kernel_launch(void* const* d_in, const int* in_sizes, int n_in,
                              void* d_out, int out_size) {
    const float* x   = (const float*)d_in[0];
    const void*  ei  = d_in[1];
    const float* W1  = (const float*)d_in[2];
    const float* as1 = (const float*)d_in[3];
    const float* ad1 = (const float*)d_in[4];
    const float* b1  = (const float*)d_in[5];
    const float* W2  = (const float*)d_in[6];
    const float* as2 = (const float*)d_in[7];
    const float* ad2 = (const float*)d_in[8];
    const float* b2  = (const float*)d_in[9];
    float* out = (float*)d_out;

    // R7 root cause: resolve true device addresses of __device__ symbols
    // used as kernel args (host-shadow writes are silently absorbed via ATS).
    float *h1p = nullptr, *x1p = nullptr, *h2p = nullptr;
    cudaGetSymbolAddress((void**)&h1p, g_h1);
    cudaGetSymbolAddress((void**)&x1p, g_x1);
    cudaGetSymbolAddress((void**)&h2p, g_h2);

    detect_zero_k<<<(NN + 255) / 256, 256>>>((const long long*)ei);
    count_k<<<(ET + 255) / 256, 256>>>(ei);
    scan_fast_k<<<1, 1024>>>();
    scatter_k<<<(ET + 255) / 256, 256>>>(ei);

    // layer 1: h1 = x @ W1  (20000x256 @ 256x256) on tensor cores
    { dim3 g(HC / BN, (NN + BM - 1) / BM); wgemm_k<<<g, 256>>>(x, W1, h1p, NN, HC, KIN); }
    att1_k<<<(NN * H1 + 255) / 256, 256>>>(as1, ad1);
    gat1_k<<<NN, 256>>>(b1);

    // layer 2: h2 = x1 @ W2  (20000x256 @ 256x64) on tensor cores
    { dim3 g(C2 / BN, (NN + BM - 1) / BM); wgemm_k<<<g, 256>>>(x1p, W2, h2p, NN, C2, HC); }
    att2_k<<<(NN + 255) / 256, 256>>>(as2, ad2);
    gat2_k<<<NN, 64>>>(b2, out);
}

// round 13
// speedup vs baseline: 1.4193x; 1.4193x over previous
#include <cuda_runtime.h>
#include <cuda_fp16.h>
#include <math.h>

// GATNET: N=20000, E=640000, IN=256, H=4, OUT=64
#define NN   20000
#define EE   640000
#define ET   (EE + NN)
#define KIN  256
#define HC   256
#define H1   4
#define C1   64
#define C2   64

__device__ __half g_h1h[NN * HC];   // fp16 h1 (only form needed downstream)
__device__ float  g_x1[NN * HC];
__device__ __half g_h2h[NN * C2];
__device__ float  g_as1[NN * H1];
__device__ float  g_ad1[NN * H1];
__device__ float  g_as2[NN];
__device__ float  g_ad2[NN];
__device__ int    g_cnt[NN];
__device__ int    g_ptr[NN + 1];
__device__ int    g_cur[NN];
__device__ int    g_csr_src[ET];
__device__ float  g_w1c[ET * H1];
__device__ float  g_w2c[ET];
__device__ int    g_is64;

// ---------------- dtype probe + zero counts (fused) ----------------
__global__ void detect_zero_k(const long long* __restrict__ ei64) {
    int t = blockIdx.x * blockDim.x + threadIdx.x;
    if (t < NN) g_cnt[t] = 0;
    if (blockIdx.x == 0) {
        __shared__ int bad;
        if (threadIdx.x == 0) bad = 0;
        __syncthreads();
        for (int i = threadIdx.x; i < 2048; i += blockDim.x) {
            long long v = ei64[i];
            if (v < 0 || v >= NN) bad = 1;
        }
        __syncthreads();
        if (threadIdx.x == 0) g_is64 = bad ? 0 : 1;
    }
}

__device__ __forceinline__ void load_edge(const void* __restrict__ ei, int e, int& s, int& d) {
    if (e >= EE) { s = d = e - EE; return; }
    if (g_is64) {
        const long long* p = (const long long*)ei;
        s = (int)p[e]; d = (int)p[EE + e];
    } else {
        const int* p = (const int*)ei;
        s = p[e]; d = p[EE + e];
    }
}

// count: needs dst only (half the index traffic)
__global__ void count_k(const void* __restrict__ ei) {
    int e = blockIdx.x * blockDim.x + threadIdx.x;
    if (e >= ET) return;
    int d;
    if (e >= EE) d = e - EE;
    else if (g_is64) d = (int)((const long long*)ei)[EE + e];
    else             d = ((const int*)ei)[EE + e];
    if ((unsigned)d < NN) atomicAdd(&g_cnt[d], 1);
}

// ---------------- fast single-block scan ----------------
__global__ __launch_bounds__(1024) void scan_fast_k() {
    const int T = 20;
    int tid = threadIdx.x;
    int base = tid * T;
    int pre[T];
    int s = 0;
#pragma unroll
    for (int i = 0; i < T; i++) {
        int idx = base + i;
        int v = (idx < NN) ? g_cnt[idx] : 0;
        pre[i] = s; s += v;
    }
    int lane = tid & 31, wid = tid >> 5;
    int incl = s;
#pragma unroll
    for (int o = 1; o < 32; o <<= 1) {
        int n = __shfl_up_sync(0xffffffffu, incl, o);
        if (lane >= o) incl += n;
    }
    __shared__ int wsum[32];
    if (lane == 31) wsum[wid] = incl;
    __syncthreads();
    if (wid == 0) {
        int v = wsum[lane];
        int wi = v;
#pragma unroll
        for (int o = 1; o < 32; o <<= 1) {
            int n = __shfl_up_sync(0xffffffffu, wi, o);
            if (lane >= o) wi += n;
        }
        wsum[lane] = wi - v;
    }
    __syncthreads();
    int off = wsum[wid] + incl - s;
#pragma unroll
    for (int i = 0; i < T; i++) {
        int idx = base + i;
        if (idx < NN) { int p = off + pre[i]; g_ptr[idx] = p; g_cur[idx] = p; }
    }
    if (tid == 1023) g_ptr[NN] = off + s;
}

__global__ void scatter_k(const void* __restrict__ ei) {
    int e = blockIdx.x * blockDim.x + threadIdx.x;
    if (e >= ET) return;
    int s, d; load_edge(ei, e, s, d);
    if ((unsigned)d < NN && (unsigned)s < NN) {
        int pos = atomicAdd(&g_cur[d], 1);
        g_csr_src[pos] = s;
    }
}

// ---------------- SGEMM 64x64 + fused attention-logit epilogue ----------------
// BN=64 == head width, so blockIdx.x == head index. Writes fp16 C only, plus
// as/ad logits reduced from the register accumulators (width-16 shuffle).
__global__ __launch_bounds__(256) void sgemm_fused_k(const float* __restrict__ A,
                                                     const float* __restrict__ B,
                                                     __half* __restrict__ Ch,
                                                     const float* __restrict__ attS,
                                                     const float* __restrict__ attD,
                                                     float* __restrict__ asOut,
                                                     float* __restrict__ adOut,
                                                     int HS,     // heads stride (H1 or 1)
                                                     int M, int N, int K) {
    __shared__ float As[16][68];
    __shared__ float Bs[16][64];
    const int bn = blockIdx.x * 64;
    const int bm = blockIdx.y * 64;
    const int tid = threadIdx.x;
    const int tx = tid & 15, ty = tid >> 4;
    const int la_k = tid & 15, la_m = tid >> 4;
    const int lb_c = tid & 63, lb_k = tid >> 6;
    float acc[4][4] = {};

    for (int k0 = 0; k0 < K; k0 += 16) {
#pragma unroll
        for (int i = 0; i < 4; i++) {
            int m = la_m + i * 16;
            int gm = bm + m;
            As[la_k][m] = (gm < M) ? A[(size_t)gm * K + k0 + la_k] : 0.0f;
        }
#pragma unroll
        for (int i = 0; i < 4; i++) {
            int kk = lb_k + i * 4;
            Bs[kk][lb_c] = B[(size_t)(k0 + kk) * N + bn + lb_c];
        }
        __syncthreads();
#pragma unroll
        for (int k = 0; k < 16; k++) {
            float4 a4 = *(const float4*)&As[k][ty * 4];
            float4 b4 = *(const float4*)&Bs[k][tx * 4];
            float av[4] = {a4.x, a4.y, a4.z, a4.w};
            float bv[4] = {b4.x, b4.y, b4.z, b4.w};
#pragma unroll
            for (int i = 0; i < 4; i++)
#pragma unroll
                for (int j = 0; j < 4; j++) acc[i][j] += av[i] * bv[j];
        }
        __syncthreads();
    }

    // att vectors for my 4 columns (global col = bn + tx*4 + j; att is flat [N])
    float asv[4], adv[4];
#pragma unroll
    for (int j = 0; j < 4; j++) {
        asv[j] = attS[bn + tx * 4 + j];
        adv[j] = attD[bn + tx * 4 + j];
    }
    const int h = blockIdx.x;

#pragma unroll
    for (int i = 0; i < 4; i++) {
        int gm = bm + ty * 4 + i;
        float s = acc[i][0] * asv[0] + acc[i][1] * asv[1] + acc[i][2] * asv[2] + acc[i][3] * asv[3];
        float d = acc[i][0] * adv[0] + acc[i][1] * adv[1] + acc[i][2] * adv[2] + acc[i][3] * adv[3];
#pragma unroll
        for (int o = 8; o; o >>= 1) {
            s += __shfl_down_sync(0xffffffffu, s, o, 16);
            d += __shfl_down_sync(0xffffffffu, d, o, 16);
        }
        if (gm < M) {
            if (tx == 0) {
                asOut[(size_t)gm * HS + h] = s;
                adOut[(size_t)gm * HS + h] = d;
            }
            __half2* hp = (__half2*)&Ch[(size_t)gm * N + bn + tx * 4];
            hp[0] = __floats2half2_rn(acc[i][0], acc[i][1]);
            hp[1] = __floats2half2_rn(acc[i][2], acc[i][3]);
        }
    }
}

// ---------------- fused edge-softmax + fp16 gather, layer 1 ----------------
__global__ __launch_bounds__(256) void gat1_k(const float* __restrict__ bias1) {
    const int d = blockIdx.x;
    const int tid = threadIdx.x;
    const int p0 = g_ptr[d], p1 = g_ptr[d + 1];
    const int cnt = p1 - p0;

    float loc[H1] = {0.f, 0.f, 0.f, 0.f};
    const int items = cnt * H1;
    for (int i = tid; i < items; i += 256) {
        int j = p0 + (i >> 2);
        int h = i & 3;
        int s = g_csr_src[j];
        float x = g_as1[s * H1 + h] + g_ad1[d * H1 + h];
        x = (x > 0.f) ? x : 0.2f * x;
        x = fmaxf(x, -60.f);
        float w = expf(x);
        g_w1c[j * H1 + h] = w;
        loc[h] += w;
    }
#pragma unroll
    for (int h = 0; h < H1; h++)
#pragma unroll
        for (int o = 16; o; o >>= 1) loc[h] += __shfl_down_sync(0xffffffffu, loc[h], o);
    __shared__ float sw[8][H1];
    if ((tid & 31) == 0)
#pragma unroll
        for (int h = 0; h < H1; h++) sw[tid >> 5][h] = loc[h];
    __syncthreads();
    __shared__ float sinv[H1];
    if (tid < H1) {
        float s = 0.f;
#pragma unroll
        for (int w = 0; w < 8; w++) s += sw[w][tid];
        sinv[tid] = 1.0f / (s + 1e-16f);
    }
    __syncthreads();

    const int eo = tid >> 7;
    const int fi = tid & 127;
    const int f  = fi * 2;
    const int h  = f >> 6;
    const float inv = sinv[h];
    float2 acc = make_float2(0.f, 0.f);
    const __half2* h1h = (const __half2*)g_h1h;
    for (int j = p0 + eo; j < p1; j += 2) {
        int s = g_csr_src[j];
        float w = g_w1c[j * H1 + h];
        float2 v = __half22float2(h1h[(size_t)s * (HC / 2) + fi]);
        acc.x += w * v.x;
        acc.y += w * v.y;
    }
    __shared__ float2 part[128];
    if (eo == 1) part[fi] = acc;
    __syncthreads();
    if (eo == 0) {
        acc.x += part[fi].x;
        acc.y += part[fi].y;
        float v0 = acc.x * inv + bias1[f];
        float v1 = acc.y * inv + bias1[f + 1];
        v0 = (v0 > 0.f) ? v0 : expm1f(v0);
        v1 = (v1 > 0.f) ? v1 : expm1f(v1);
        g_x1[(size_t)d * HC + f]     = v0;
        g_x1[(size_t)d * HC + f + 1] = v1;
    }
}

// ---------------- fused edge-softmax + fp16 gather, layer 2 ----------------
__global__ __launch_bounds__(64) void gat2_k(const float* __restrict__ bias2,
                                             float* __restrict__ out) {
    const int d = blockIdx.x;
    const int tid = threadIdx.x;
    const int p0 = g_ptr[d], p1 = g_ptr[d + 1];
    const int cnt = p1 - p0;

    float loc = 0.f;
    const float ad = g_ad2[d];
    for (int i = tid; i < cnt; i += 64) {
        int j = p0 + i;
        int s = g_csr_src[j];
        float x = g_as2[s] + ad;
        x = (x > 0.f) ? x : 0.2f * x;
        x = fmaxf(x, -60.f);
        float w = expf(x);
        g_w2c[j] = w;
        loc += w;
    }
#pragma unroll
    for (int o = 16; o; o >>= 1) loc += __shfl_down_sync(0xffffffffu, loc, o);
    __shared__ float sw2[2];
    if ((tid & 31) == 0) sw2[tid >> 5] = loc;
    __syncthreads();
    __shared__ float sinv2;
    if (tid == 0) sinv2 = 1.0f / (sw2[0] + sw2[1] + 1e-16f);
    __syncthreads();

    const int eo = tid >> 5;
    const int fi = tid & 31;
    const int f  = fi * 2;
    const float inv = sinv2;
    float2 acc = make_float2(0.f, 0.f);
    const __half2* h2h = (const __half2*)g_h2h;
    for (int j = p0 + eo; j < p1; j += 2) {
        int s = g_csr_src[j];
        float w = g_w2c[j];
        float2 v = __half22float2(h2h[(size_t)s * (C2 / 2) + fi]);
        acc.x += w * v.x;
        acc.y += w * v.y;
    }
    __shared__ float2 part2[32];
    if (eo == 1) part2[fi] = acc;
    __syncthreads();
    if (eo == 0) {
        acc.x += part2[fi].x;
        acc.y += part2[fi].y;
        out[(size_t)d * C2 + f]     = acc.x * inv + bias2[f];
        out[(size_t)d * C2 + f + 1] = acc.y * inv + bias2[f + 1];
    }
}

// ---------------- launch ----------------
extern "C" void kernel_launch(void* const* d_in, const int* in_sizes, int n_in,
                              void* d_out, int out_size) {
    const float* x   = (const float*)d_in[0];
    const void*  ei  = d_in[1];
    const float* W1  = (const float*)d_in[2];
    const float* as1 = (const float*)d_in[3];
    const float* ad1 = (const float*)d_in[4];
    const float* b1  = (const float*)d_in[5];
    const float* W2  = (const float*)d_in[6];
    const float* as2 = (const float*)d_in[7];
    const float* ad2 = (const float*)d_in[8];
    const float* b2  = (const float*)d_in[9];
    float* out = (float*)d_out;

    // R7 root cause: resolve true device addresses of __device__ symbols
    // used as kernel args (host-shadow writes are silently absorbed via ATS).
    __half *h1hp = nullptr, *h2hp = nullptr;
    float  *x1p = nullptr, *as1p = nullptr, *ad1p = nullptr, *as2p = nullptr, *ad2p = nullptr;
    cudaGetSymbolAddress((void**)&h1hp, g_h1h);
    cudaGetSymbolAddress((void**)&h2hp, g_h2h);
    cudaGetSymbolAddress((void**)&x1p,  g_x1);
    cudaGetSymbolAddress((void**)&as1p, g_as1);
    cudaGetSymbolAddress((void**)&ad1p, g_ad1);
    cudaGetSymbolAddress((void**)&as2p, g_as2);
    cudaGetSymbolAddress((void**)&ad2p, g_ad2);

    detect_zero_k<<<(NN + 255) / 256, 256>>>((const long long*)ei);
    count_k<<<(ET + 255) / 256, 256>>>(ei);
    scan_fast_k<<<1, 1024>>>();
    scatter_k<<<(ET + 255) / 256, 256>>>(ei);

    // layer 1: h1 = x @ W1 (fp16 out) + fused att1 logits
    { dim3 g(HC / 64, (NN + 63) / 64);
      sgemm_fused_k<<<g, 256>>>(x, W1, h1hp, as1, ad1, as1p, ad1p, H1, NN, HC, KIN); }
    gat1_k<<<NN, 256>>>(b1);

    // layer 2: h2 = x1 @ W2 (fp16 out) + fused att2 logits
    { dim3 g(C2 / 64, (NN + 63) / 64);
      sgemm_fused_k<<<g, 256>>>(x1p, W2, h2hp, as2, ad2, as2p, ad2p, 1, NN, C2, HC); }
    gat2_k<<<NN, 64>>>(b2, out);
}